// round 3
// baseline (speedup 1.0000x reference)
#include <cuda_runtime.h>
#include <math.h>
#include <stdint.h>

#define CC 256
#define NN 16384
#define BB 4
#define BCN (CC*NN)

#define EGELU 0
#define ESOFT 1
#define EIDENT 2
#define EATTN 3

// ---------------- scratch ----------------
__device__ float g_q [BB*BCN];
__device__ float g_k [BB*BCN];
__device__ float g_v [BB*BCN];
__device__ float g_g [BB*BCN];
__device__ float g_kvp[BB*16*CC*CC];
__device__ float g_kvT[BB*CC*CC];
__device__ float g_ks [BB*CC];
__device__ float g_ab [2*BB*CC];

// ---------------- helpers ----------------
__device__ __forceinline__ void cpa16(float* s, const float* g){
    unsigned a = (unsigned)__cvta_generic_to_shared(s);
    asm volatile("cp.async.cg.shared.global [%0], [%1], 16;\n" :: "r"(a), "l"(g));
}
__device__ __forceinline__ void cpacommit(){ asm volatile("cp.async.commit_group;\n"); }
__device__ __forceinline__ void cpawait(){ asm volatile("cp.async.wait_group 0;\n"); }
__device__ __forceinline__ void mma8(float* d, const unsigned* a, unsigned b0, unsigned b1){
    asm volatile(
      "mma.sync.aligned.m16n8k8.row.col.f32.tf32.tf32.f32 "
      "{%0,%1,%2,%3},{%4,%5,%6,%7},{%8,%9},{%0,%1,%2,%3};\n"
      : "+f"(d[0]), "+f"(d[1]), "+f"(d[2]), "+f"(d[3])
      : "r"(a[0]), "r"(a[1]), "r"(a[2]), "r"(a[3]), "r"(b0), "r"(b1));
}
__device__ __forceinline__ unsigned bits(float f){ return __float_as_uint(f); }
__device__ __forceinline__ float geluf(float x){
    return 0.5f * x * (1.0f + erff(x * 0.70710678118654752440f));
}
__device__ __forceinline__ float softplusf(float x){
    return fmaxf(x, 0.0f) + log1pf(expf(-fabsf(x)));
}
__device__ __forceinline__ float epi_apply(int EPI, float x){
    if (EPI == EGELU) return geluf(x);
    if (EPI == ESOFT) return softplusf(x);
    return x;
}

// ---------------- per-(b,c) norm stats: alpha = rs, beta = -mu*rs ----------
__global__ __launch_bounds__(256) void stats_kernel(
    const float* __restrict__ x, float* __restrict__ ab)
{
    const long base = (long)blockIdx.x * NN;
    const float4* xp = (const float4*)(x + base);
    const int tid = threadIdx.x;
    float s = 0.f, s2 = 0.f;
    #pragma unroll
    for (int i = 0; i < 16; ++i){
        float4 t = xp[tid + i*256];
        s  += t.x + t.y + t.z + t.w;
        s2 += t.x*t.x + t.y*t.y + t.z*t.z + t.w*t.w;
    }
    #pragma unroll
    for (int o = 16; o; o >>= 1){
        s  += __shfl_xor_sync(0xffffffffu, s,  o);
        s2 += __shfl_xor_sync(0xffffffffu, s2, o);
    }
    __shared__ float sh[16];
    const int w = tid >> 5, lane = tid & 31;
    if (lane == 0){ sh[w] = s; sh[8+w] = s2; }
    __syncthreads();
    if (tid == 0){
        float ts = 0.f, ts2 = 0.f;
        #pragma unroll
        for (int i = 0; i < 8; ++i){ ts += sh[i]; ts2 += sh[8+i]; }
        float mu  = ts * (1.0f/NN);
        float var = ts2 * (1.0f/NN) - mu*mu;
        float rs  = rsqrtf(var + 1e-5f);
        ab[blockIdx.x] = rs;
        ab[BB*CC + blockIdx.x] = -mu*rs;
    }
}

// ---------------- ksum (scaled by 1/sqrt(C)) --------------------------------
__global__ __launch_bounds__(256) void ksum_kernel(
    const float* __restrict__ k, float* __restrict__ ks)
{
    const long base = (long)blockIdx.x * NN;
    const float4* kp = (const float4*)(k + base);
    const int tid = threadIdx.x;
    float s = 0.f;
    #pragma unroll
    for (int i = 0; i < 16; ++i){
        float4 t = kp[tid + i*256];
        s += t.x + t.y + t.z + t.w;
    }
    #pragma unroll
    for (int o = 16; o; o >>= 1) s += __shfl_xor_sync(0xffffffffu, s, o);
    __shared__ float sh[8];
    const int w = tid >> 5, lane = tid & 31;
    if (lane == 0) sh[w] = s;
    __syncthreads();
    if (tid == 0){
        float ts = 0.f;
        #pragma unroll
        for (int i = 0; i < 8; ++i) ts += sh[i];
        ks[blockIdx.x] = ts * (1.0f/16.0f);
    }
}

// ---------------- fused (dual) GEMM ------------------------------------------
// Stage A: S = epi1(W1 . norm?(X) + b1)   [256 x 64 per block, S in smem]
// Stage B (optional): Y = epi2(W2 . S + b2)
struct MP {
    const float* W1[2]; const float* B1[2];
    const float* W2[2]; const float* B2[2];
    const float* X;
    float*       Y[2];
    const float* Vp; const float* Gp; const float* ksp;
    const float* AB;
    int w1Batched;
};

template<int TWO_STAGE, int NORM, int EPI1, int EPI2, int ZFUSE>
__global__ __launch_bounds__(256) void mega_kernel(MP p)
{
    extern __shared__ float sm[];
    float* WS = sm;                  // 2 x 256x36
    float* XS = sm + 2*9216;         // 2 x 32x72
    float* EX = XS + 2*2304;         // alpha(256)|beta(256)|ks(256)|z(64)
    float* S  = EX + 832;            // 256x72 (TWO_STAGE only)

    const int tid = threadIdx.x;
    const int lane = tid & 31, w = tid >> 5;
    const int lq = lane >> 2, lr = lane & 3;
    const int y = blockIdx.y;
    const int b = blockIdx.z;
    const long n0 = (long)blockIdx.x * 64;
    const float* W1 = p.W1[y] + (p.w1Batched ? (long)b*CC*CC : 0);
    const float* Xb = p.X + (long)b*BCN;

    float* ALs = EX;
    float* BEs = EX + 256;
    float* KSs = EX + 512;
    float* ZSs = EX + 768;

    if (NORM){
        ALs[tid] = p.AB[b*CC + tid];
        BEs[tid] = p.AB[BB*CC + b*CC + tid];
    }
    if (ZFUSE) KSs[tid] = p.ksp[b*CC + tid];

    // ---- stage A prologue ----
    #pragma unroll
    for (int i = 0; i < 8; ++i){
        int idx = tid + i*256, r = idx >> 3, c4 = idx & 7;
        cpa16(WS + r*36 + c4*4, W1 + (long)r*256 + c4*4);
    }
    #pragma unroll
    for (int i = 0; i < 2; ++i){
        int idx = tid + i*256, r = idx >> 4, c4 = idx & 15;
        cpa16(XS + r*72 + c4*4, Xb + (long)r*NN + n0 + c4*4);
    }
    cpacommit();

    float acc[2][8][4];
    #pragma unroll
    for (int mt = 0; mt < 2; ++mt)
        #pragma unroll
        for (int nt = 0; nt < 8; ++nt)
            #pragma unroll
            for (int i = 0; i < 4; ++i) acc[mt][nt][i] = 0.f;
    float zreg = 0.f;

    #pragma unroll 1
    for (int kc = 0; kc < 8; ++kc){
        cpawait();
        __syncthreads();
        if (kc < 7){
            float* ws2 = WS + ((kc+1)&1)*9216;
            float* xs2 = XS + ((kc+1)&1)*2304;
            const int kb = (kc+1)*32;
            #pragma unroll
            for (int i = 0; i < 8; ++i){
                int idx = tid + i*256, r = idx >> 3, c4 = idx & 7;
                cpa16(ws2 + r*36 + c4*4, W1 + (long)r*256 + kb + c4*4);
            }
            #pragma unroll
            for (int i = 0; i < 2; ++i){
                int idx = tid + i*256, r = idx >> 4, c4 = idx & 15;
                cpa16(xs2 + r*72 + c4*4, Xb + (long)(kb+r)*NN + n0 + c4*4);
            }
            cpacommit();
        }
        float* xcur = XS + (kc&1)*2304;
        if (NORM){
            #pragma unroll
            for (int i = 0; i < 8; ++i){
                int idx = tid + i*256, r = idx >> 6, c = idx & 63;
                xcur[r*72 + c] = fmaf(xcur[r*72 + c], ALs[kc*32 + r], BEs[kc*32 + r]);
            }
            __syncthreads();
        }
        if (ZFUSE && tid < 64){
            #pragma unroll
            for (int kk = 0; kk < 32; ++kk)
                zreg = fmaf(xcur[kk*72 + tid], KSs[kc*32 + kk], zreg);
        }
        const float* wsA = WS + (kc&1)*9216 + (w*32 + lq)*36 + lr;
        const float* xsB = xcur + lr*72 + lq;
        #pragma unroll
        for (int k8 = 0; k8 < 4; ++k8){
            const int kb = k8*8;
            unsigned a[2][4];
            #pragma unroll
            for (int mt = 0; mt < 2; ++mt){
                a[mt][0] = bits(wsA[(mt*16  )*36 + kb    ]);
                a[mt][1] = bits(wsA[(mt*16+8)*36 + kb    ]);
                a[mt][2] = bits(wsA[(mt*16  )*36 + kb + 4]);
                a[mt][3] = bits(wsA[(mt*16+8)*36 + kb + 4]);
            }
            #pragma unroll
            for (int nt = 0; nt < 8; ++nt){
                unsigned b0 = bits(xsB[ kb   *72 + nt*8]);
                unsigned b1 = bits(xsB[(kb+4)*72 + nt*8]);
                mma8(acc[0][nt], a[0], b0, b1);
                mma8(acc[1][nt], a[1], b0, b1);
            }
        }
        __syncthreads();
    }

    if (ZFUSE){
        if (tid < 64) ZSs[tid] = 1.0f / (zreg + (float)NN);
        __syncthreads();
    }

    // ---- stage A epilogue ----
    {
        float* Yb = p.Y[y] + (long)b*BCN;
        #pragma unroll
        for (int mt = 0; mt < 2; ++mt){
            #pragma unroll
            for (int half = 0; half < 2; ++half){
                const int r = w*32 + mt*16 + lq + half*8;
                float bi = 0.f;
                if (EPI1 != EATTN) bi = p.B1[y][r];
                const long rowoff = (long)r*NN + n0;
                #pragma unroll
                for (int nt = 0; nt < 8; ++nt){
                    const int c = nt*8 + lr*2;
                    float x0 = acc[mt][nt][half*2+0] + bi;
                    float x1 = acc[mt][nt][half*2+1] + bi;
                    float2 o;
                    if (EPI1 == EATTN){
                        const float2 vv = *(const float2*)(p.Vp + (long)b*BCN + rowoff + c);
                        const float2 gg = *(const float2*)(p.Gp + (long)b*BCN + rowoff + c);
                        o.x = (x0 + vv.x) * ZSs[c]   * gg.x;
                        o.y = (x1 + vv.y) * ZSs[c+1] * gg.y;
                    } else {
                        o.x = epi_apply(EPI1, x0);
                        o.y = epi_apply(EPI1, x1);
                    }
                    if (TWO_STAGE) *(float2*)(S + r*72 + c) = o;
                    else           *(float2*)(Yb + rowoff + c) = o;
                }
            }
        }
    }

    if (!TWO_STAGE) return;

    // ---- stage B: Y = epi2(W2 . S + b2) ----
    const float* W2 = p.W2[y];
    #pragma unroll
    for (int i = 0; i < 8; ++i){
        int idx = tid + i*256, r = idx >> 3, c4 = idx & 7;
        cpa16(WS + r*36 + c4*4, W2 + (long)r*256 + c4*4);
    }
    cpacommit();

    float acc2[2][8][4];
    #pragma unroll
    for (int mt = 0; mt < 2; ++mt)
        #pragma unroll
        for (int nt = 0; nt < 8; ++nt)
            #pragma unroll
            for (int i = 0; i < 4; ++i) acc2[mt][nt][i] = 0.f;

    #pragma unroll 1
    for (int kc = 0; kc < 8; ++kc){
        cpawait();
        __syncthreads();
        if (kc < 7){
            float* ws2 = WS + ((kc+1)&1)*9216;
            const int kb = (kc+1)*32;
            #pragma unroll
            for (int i = 0; i < 8; ++i){
                int idx = tid + i*256, r = idx >> 3, c4 = idx & 7;
                cpa16(ws2 + r*36 + c4*4, W2 + (long)r*256 + kb + c4*4);
            }
            cpacommit();
        }
        const float* wsA = WS + (kc&1)*9216 + (w*32 + lq)*36 + lr;
        const float* sB  = S + (kc*32 + lr)*72 + lq;
        #pragma unroll
        for (int k8 = 0; k8 < 4; ++k8){
            const int kb = k8*8;
            unsigned a[2][4];
            #pragma unroll
            for (int mt = 0; mt < 2; ++mt){
                a[mt][0] = bits(wsA[(mt*16  )*36 + kb    ]);
                a[mt][1] = bits(wsA[(mt*16+8)*36 + kb    ]);
                a[mt][2] = bits(wsA[(mt*16  )*36 + kb + 4]);
                a[mt][3] = bits(wsA[(mt*16+8)*36 + kb + 4]);
            }
            #pragma unroll
            for (int nt = 0; nt < 8; ++nt){
                unsigned b0 = bits(sB[ kb   *72 + nt*8]);
                unsigned b1 = bits(sB[(kb+4)*72 + nt*8]);
                mma8(acc2[0][nt], a[0], b0, b1);
                mma8(acc2[1][nt], a[1], b0, b1);
            }
        }
        __syncthreads();
    }

    {
        float* Yb = p.Y[y] + (long)b*BCN;
        #pragma unroll
        for (int mt = 0; mt < 2; ++mt){
            #pragma unroll
            for (int half = 0; half < 2; ++half){
                const int r = w*32 + mt*16 + lq + half*8;
                const float bi = p.B2[y][r];
                const long rowoff = (long)r*NN + n0;
                #pragma unroll
                for (int nt = 0; nt < 8; ++nt){
                    const int c = nt*8 + lr*2;
                    float x0 = acc2[mt][nt][half*2+0] + bi;
                    float x1 = acc2[mt][nt][half*2+1] + bi;
                    float2 o;
                    o.x = epi_apply(EPI2, x0);
                    o.y = epi_apply(EPI2, x1);
                    *(float2*)(Yb + rowoff + c) = o;
                }
            }
        }
    }
}

// ---------------- kv partial GEMM: P[b][chunk] = k-tile . v-tile^T ------------
__global__ __launch_bounds__(256) void kv_kernel(
    const float* __restrict__ K, const float* __restrict__ V, float* __restrict__ P)
{
    extern __shared__ float sm[];
    float* AS = sm;
    float* BS = sm + 2*4608;
    const int tid = threadIdx.x, lane = tid & 31, w = tid >> 5;
    const int lq = lane >> 2, lr = lane & 3;
    const int wm = w & 3, wn = w >> 2;
    const int c0 = (blockIdx.x & 1) * 128;
    const int d0 = (blockIdx.x >> 1) * 128;
    const int chunk = blockIdx.y;
    const int b = blockIdx.z;
    const float* Kb = K + (long)b*BCN;
    const float* Vb = V + (long)b*BCN;
    const long nbase = (long)chunk * 1024;

    {
        const long nb = nbase;
        #pragma unroll
        for (int i = 0; i < 4; ++i){
            int idx = tid + i*256, r = idx >> 3, c4 = idx & 7;
            cpa16(AS + r*36 + c4*4, Kb + (long)(c0+r)*NN + nb + c4*4);
            cpa16(BS + r*36 + c4*4, Vb + (long)(d0+r)*NN + nb + c4*4);
        }
        cpacommit();
    }

    float acc[2][8][4];
    #pragma unroll
    for (int mt = 0; mt < 2; ++mt)
        #pragma unroll
        for (int nt = 0; nt < 8; ++nt)
            #pragma unroll
            for (int i = 0; i < 4; ++i) acc[mt][nt][i] = 0.f;

    #pragma unroll 1
    for (int it = 0; it < 32; ++it){
        cpawait();
        __syncthreads();
        if (it < 31){
            float* as2 = AS + ((it+1)&1)*4608;
            float* bs2 = BS + ((it+1)&1)*4608;
            const long nb = nbase + (long)(it+1)*32;
            #pragma unroll
            for (int i = 0; i < 4; ++i){
                int idx = tid + i*256, r = idx >> 3, c4 = idx & 7;
                cpa16(as2 + r*36 + c4*4, Kb + (long)(c0+r)*NN + nb + c4*4);
                cpa16(bs2 + r*36 + c4*4, Vb + (long)(d0+r)*NN + nb + c4*4);
            }
            cpacommit();
        }
        const float* asA = AS + (it&1)*4608 + (wm*32 + lq)*36 + lr;
        const float* bsB = BS + (it&1)*4608 + (wn*64 + lq)*36 + lr;
        #pragma unroll
        for (int k8 = 0; k8 < 4; ++k8){
            const int kb = k8*8;
            unsigned a[2][4];
            #pragma unroll
            for (int mt = 0; mt < 2; ++mt){
                a[mt][0] = bits(asA[(mt*16  )*36 + kb    ]);
                a[mt][1] = bits(asA[(mt*16+8)*36 + kb    ]);
                a[mt][2] = bits(asA[(mt*16  )*36 + kb + 4]);
                a[mt][3] = bits(asA[(mt*16+8)*36 + kb + 4]);
            }
            #pragma unroll
            for (int nt = 0; nt < 8; ++nt){
                unsigned b0 = bits(bsB[nt*8*36 + kb    ]);
                unsigned b1 = bits(bsB[nt*8*36 + kb + 4]);
                mma8(acc[0][nt], a[0], b0, b1);
                mma8(acc[1][nt], a[1], b0, b1);
            }
        }
        __syncthreads();
    }

    float* Pb = P + (long)(b*16 + chunk)*CC*CC;
    #pragma unroll
    for (int mt = 0; mt < 2; ++mt){
        #pragma unroll
        for (int half = 0; half < 2; ++half){
            const int r = c0 + wm*32 + mt*16 + lq + half*8;
            #pragma unroll
            for (int nt = 0; nt < 8; ++nt){
                const int d = d0 + wn*64 + nt*8 + lr*2;
                float2 o;
                o.x = acc[mt][nt][half*2+0];
                o.y = acc[mt][nt][half*2+1];
                *(float2*)(Pb + (long)r*CC + d) = o;
            }
        }
    }
}

// ---------------- kv reduce (+transpose, fold 1/sqrt(C)) ----------------------
__global__ __launch_bounds__(256) void kvred_kernel(
    const float* __restrict__ P, float* __restrict__ kvT)
{
    const int o = blockIdx.x * 256 + threadIdx.x;
    const int b = o >> 16;
    const int c = (o >> 8) & 255;
    const int d = o & 255;
    float s = 0.f;
    #pragma unroll
    for (int ch = 0; ch < 16; ++ch)
        s += P[((long)(b*16 + ch)*256 + c)*256 + d];
    kvT[((long)b*256 + d)*256 + c] = s * (1.0f/16.0f);
}

// ---------------- host side ---------------------------------------------------
static const size_t SMEM_DUAL   = (size_t)(2*9216 + 2*2304 + 832 + 256*72) * sizeof(float); // 169216
static const size_t SMEM_SINGLE = (size_t)(2*9216 + 2*2304 + 832) * sizeof(float);          // 95488
static const size_t KV_SMEM     = (size_t)(4*4608) * sizeof(float);

extern "C" void kernel_launch(void* const* d_in, const int* in_sizes, int n_in,
                              void* d_out, int out_size)
{
    (void)in_sizes; (void)n_in; (void)out_size;
    const float* x   = (const float*)d_in[0];
    const float* Wq1 = (const float*)d_in[1];  const float* bq1 = (const float*)d_in[2];
    const float* Wq2 = (const float*)d_in[3];  const float* bq2 = (const float*)d_in[4];
    const float* Wk1 = (const float*)d_in[5];  const float* bk1 = (const float*)d_in[6];
    const float* Wk2 = (const float*)d_in[7];  const float* bk2 = (const float*)d_in[8];
    const float* Wv  = (const float*)d_in[9];  const float* bv  = (const float*)d_in[10];
    const float* Wg  = (const float*)d_in[11]; const float* bg  = (const float*)d_in[12];
    const float* Wo  = (const float*)d_in[13]; const float* bo  = (const float*)d_in[14];
    float* out = (float*)d_out;

    float *q, *k, *v, *g, *kvp, *kvT, *ks, *ab;
    cudaGetSymbolAddress((void**)&q,   g_q);
    cudaGetSymbolAddress((void**)&k,   g_k);
    cudaGetSymbolAddress((void**)&v,   g_v);
    cudaGetSymbolAddress((void**)&g,   g_g);
    cudaGetSymbolAddress((void**)&kvp, g_kvp);
    cudaGetSymbolAddress((void**)&kvT, g_kvT);
    cudaGetSymbolAddress((void**)&ks,  g_ks);
    cudaGetSymbolAddress((void**)&ab,  g_ab);

    cudaFuncSetAttribute((const void*)mega_kernel<1,1,EGELU,ESOFT,0>,
                         cudaFuncAttributeMaxDynamicSharedMemorySize, (int)SMEM_DUAL);
    cudaFuncSetAttribute((const void*)mega_kernel<0,1,EGELU,EIDENT,0>,
                         cudaFuncAttributeMaxDynamicSharedMemorySize, (int)SMEM_SINGLE);
    cudaFuncSetAttribute((const void*)mega_kernel<1,0,EATTN,EIDENT,1>,
                         cudaFuncAttributeMaxDynamicSharedMemorySize, (int)SMEM_DUAL);
    cudaFuncSetAttribute((const void*)kv_kernel,
                         cudaFuncAttributeMaxDynamicSharedMemorySize, (int)KV_SMEM);

    // 1. norm stats
    stats_kernel<<<BB*CC, 256>>>(x, ab);

    // 2. q-chain and k-chain (dual GEMM, gelu -> softplus), normalized input
    {
        MP p = {};
        p.W1[0]=Wq1; p.B1[0]=bq1; p.W2[0]=Wq2; p.B2[0]=bq2; p.Y[0]=q;
        p.W1[1]=Wk1; p.B1[1]=bk1; p.W2[1]=Wk2; p.B2[1]=bk2; p.Y[1]=k;
        p.X = x; p.AB = ab; p.w1Batched = 0;
        dim3 grid(NN/64, 2, BB);
        mega_kernel<1,1,EGELU,ESOFT,0><<<grid, 256, SMEM_DUAL>>>(p);
    }

    // 3. v and g (single GEMM, gelu), normalized input
    {
        MP p = {};
        p.W1[0]=Wv; p.B1[0]=bv; p.Y[0]=v;
        p.W1[1]=Wg; p.B1[1]=bg; p.Y[1]=g;
        p.X = x; p.AB = ab; p.w1Batched = 0;
        dim3 grid(NN/64, 2, BB);
        mega_kernel<0,1,EGELU,EIDENT,0><<<grid, 256, SMEM_SINGLE>>>(p);
    }

    // 4. ksum (scaled), kv partials + reduce(+transpose, 1/sqrt(C))
    ksum_kernel<<<BB*CC, 256>>>(k, ks);
    {
        dim3 grid(4, 16, BB);
        kv_kernel<<<grid, 256, KV_SMEM>>>(k, v, kvp);
    }
    kvred_kernel<<<BB*CC, 256>>>(kvp, kvT);

    // 5. attn + final conv (dual GEMM): S=(kvT.q+v)*z*g  ->  out=Wo.S+bo
    //    z computed in-block from ks and streamed q
    {
        MP p = {};
        p.W1[0]=kvT; p.B1[0]=nullptr; p.W2[0]=Wo; p.B2[0]=bo; p.Y[0]=out;
        p.X = q; p.Vp = v; p.Gp = g; p.ksp = ks; p.w1Batched = 1;
        dim3 grid(NN/64, 1, BB);
        mega_kernel<1,0,EATTN,EIDENT,1><<<grid, 256, SMEM_DUAL>>>(p);
    }
}

// round 4
// speedup vs baseline: 1.1817x; 1.1817x over previous
#include <cuda_runtime.h>
#include <math.h>
#include <stdint.h>

#define CC 256
#define NN 16384
#define BB 4
#define BCN (CC*NN)

#define EGELU 0
#define ESOFT 1
#define EIDENT 2
#define EATTN 3

// ---------------- scratch ----------------
__device__ float g_t [BB*BCN];
__device__ float g_t2[BB*BCN];
__device__ float g_q [BB*BCN];
__device__ float g_k [BB*BCN];
__device__ float g_v [BB*BCN];
__device__ float g_g [BB*BCN];
__device__ float g_kvp[BB*16*CC*CC];
__device__ float g_kvT[BB*CC*CC];
__device__ float g_ks [BB*CC];
__device__ float g_ab [2*BB*CC];

// ---------------- helpers ----------------
__device__ __forceinline__ void cpa16(float* s, const float* g){
    unsigned a = (unsigned)__cvta_generic_to_shared(s);
    asm volatile("cp.async.cg.shared.global [%0], [%1], 16;\n" :: "r"(a), "l"(g));
}
__device__ __forceinline__ void cpacommit(){ asm volatile("cp.async.commit_group;\n"); }
__device__ __forceinline__ void cpawait(){ asm volatile("cp.async.wait_group 0;\n"); }
__device__ __forceinline__ void mma8(float* d, const unsigned* a, unsigned b0, unsigned b1){
    asm volatile(
      "mma.sync.aligned.m16n8k8.row.col.f32.tf32.tf32.f32 "
      "{%0,%1,%2,%3},{%4,%5,%6,%7},{%8,%9},{%0,%1,%2,%3};\n"
      : "+f"(d[0]), "+f"(d[1]), "+f"(d[2]), "+f"(d[3])
      : "r"(a[0]), "r"(a[1]), "r"(a[2]), "r"(a[3]), "r"(b0), "r"(b1));
}
__device__ __forceinline__ unsigned bits(float f){ return __float_as_uint(f); }
__device__ __forceinline__ float geluf(float x){
    return 0.5f * x * (1.0f + erff(x * 0.70710678118654752440f));
}
__device__ __forceinline__ float softplusf(float x){
    return fmaxf(x, 0.0f) + log1pf(expf(-fabsf(x)));
}
__device__ __forceinline__ float epi_apply(int EPI, float x){
    if (EPI == EGELU) return geluf(x);
    if (EPI == ESOFT) return softplusf(x);
    return x;
}

// ---------------- per-(b,c) norm stats: alpha = rs, beta = -mu*rs -----------
__global__ __launch_bounds__(256) void stats_kernel(
    const float* __restrict__ x, float* __restrict__ ab)
{
    const long base = (long)blockIdx.x * NN;
    const float4* xp = (const float4*)(x + base);
    const int tid = threadIdx.x;
    float s = 0.f, s2 = 0.f;
    #pragma unroll
    for (int i = 0; i < 16; ++i){
        float4 t = xp[tid + i*256];
        s  += t.x + t.y + t.z + t.w;
        s2 += t.x*t.x + t.y*t.y + t.z*t.z + t.w*t.w;
    }
    #pragma unroll
    for (int o = 16; o; o >>= 1){
        s  += __shfl_xor_sync(0xffffffffu, s,  o);
        s2 += __shfl_xor_sync(0xffffffffu, s2, o);
    }
    __shared__ float sh[16];
    const int w = tid >> 5, lane = tid & 31;
    if (lane == 0){ sh[w] = s; sh[8+w] = s2; }
    __syncthreads();
    if (tid == 0){
        float ts = 0.f, ts2 = 0.f;
        #pragma unroll
        for (int i = 0; i < 8; ++i){ ts += sh[i]; ts2 += sh[8+i]; }
        float mu  = ts * (1.0f/NN);
        float var = ts2 * (1.0f/NN) - mu*mu;
        float rs  = rsqrtf(var + 1e-5f);
        ab[blockIdx.x] = rs;
        ab[BB*CC + blockIdx.x] = -mu*rs;
    }
}

// ---------------- ksum (scaled by 1/sqrt(C)) ---------------------------------
__global__ __launch_bounds__(256) void ksum_kernel(
    const float* __restrict__ k, float* __restrict__ ks)
{
    const long base = (long)blockIdx.x * NN;
    const float4* kp = (const float4*)(k + base);
    const int tid = threadIdx.x;
    float s = 0.f;
    #pragma unroll
    for (int i = 0; i < 16; ++i){
        float4 t = kp[tid + i*256];
        s += t.x + t.y + t.z + t.w;
    }
    #pragma unroll
    for (int o = 16; o; o >>= 1) s += __shfl_xor_sync(0xffffffffu, s, o);
    __shared__ float sh[8];
    const int w = tid >> 5, lane = tid & 31;
    if (lane == 0) sh[w] = s;
    __syncthreads();
    if (tid == 0){
        float ts = 0.f;
        #pragma unroll
        for (int i = 0; i < 8; ++i) ts += sh[i];
        ks[blockIdx.x] = ts * (1.0f/16.0f);
    }
}

// ---------------- fused single-stage GEMM with epilogues ---------------------
// Y[y][b][m][n] = epi( sum_k W[y][m][k] * norm?(X[y][b][k][n]) + bias[y][m] )
struct MP {
    const float* W[4]; const float* B[4];
    const float* X[4]; float* Y[4];
    const float* Vp; const float* Gp; const float* ksp;
    const float* AB;
    int wBatched;
};

template<int NORM, int EPI, int ZFUSE>
__global__ __launch_bounds__(256,2) void gemm_kernel(MP p)
{
    extern __shared__ float sm[];
    float* WS = sm;                  // 2 x 256x36
    float* XS = sm + 2*9216;         // 2 x 32x72
    float* EX = XS + 2*2304;         // alpha(256)|beta(256)|ks(256)|z(64)

    const int tid = threadIdx.x;
    const int lane = tid & 31, w = tid >> 5;
    const int lq = lane >> 2, lr = lane & 3;
    const int y = blockIdx.y;
    const int b = blockIdx.z;
    const long n0 = (long)blockIdx.x * 64;
    const float* W1 = p.W[y] + (p.wBatched ? (long)b*CC*CC : 0);
    const float* Xb = p.X[y] + (long)b*BCN;

    float* ALs = EX;
    float* BEs = EX + 256;
    float* KSs = EX + 512;
    float* ZSs = EX + 768;

    if (NORM){
        ALs[tid] = p.AB[b*CC + tid];
        BEs[tid] = p.AB[BB*CC + b*CC + tid];
    }
    if (ZFUSE) KSs[tid] = p.ksp[b*CC + tid];

    // prologue
    #pragma unroll
    for (int i = 0; i < 8; ++i){
        int idx = tid + i*256, r = idx >> 3, c4 = idx & 7;
        cpa16(WS + r*36 + c4*4, W1 + (long)r*256 + c4*4);
    }
    #pragma unroll
    for (int i = 0; i < 2; ++i){
        int idx = tid + i*256, r = idx >> 4, c4 = idx & 15;
        cpa16(XS + r*72 + c4*4, Xb + (long)r*NN + n0 + c4*4);
    }
    cpacommit();

    float acc[2][8][4];
    #pragma unroll
    for (int mt = 0; mt < 2; ++mt)
        #pragma unroll
        for (int nt = 0; nt < 8; ++nt)
            #pragma unroll
            for (int i = 0; i < 4; ++i) acc[mt][nt][i] = 0.f;
    float zreg = 0.f;

    #pragma unroll 1
    for (int kc = 0; kc < 8; ++kc){
        cpawait();
        __syncthreads();
        if (kc < 7){
            float* ws2 = WS + ((kc+1)&1)*9216;
            float* xs2 = XS + ((kc+1)&1)*2304;
            const int kb = (kc+1)*32;
            #pragma unroll
            for (int i = 0; i < 8; ++i){
                int idx = tid + i*256, r = idx >> 3, c4 = idx & 7;
                cpa16(ws2 + r*36 + c4*4, W1 + (long)r*256 + kb + c4*4);
            }
            #pragma unroll
            for (int i = 0; i < 2; ++i){
                int idx = tid + i*256, r = idx >> 4, c4 = idx & 15;
                cpa16(xs2 + r*72 + c4*4, Xb + (long)(kb+r)*NN + n0 + c4*4);
            }
            cpacommit();
        }
        float* xcur = XS + (kc&1)*2304;
        if (NORM){
            #pragma unroll
            for (int i = 0; i < 8; ++i){
                int idx = tid + i*256, r = idx >> 6, c = idx & 63;
                xcur[r*72 + c] = fmaf(xcur[r*72 + c], ALs[kc*32 + r], BEs[kc*32 + r]);
            }
            __syncthreads();
        }
        if (ZFUSE && tid < 64){
            #pragma unroll
            for (int kk = 0; kk < 32; ++kk)
                zreg = fmaf(xcur[kk*72 + tid], KSs[kc*32 + kk], zreg);
        }
        // preload all A fragments for this k-chunk (ILP: decouple from B+MMA)
        const float* wsA = WS + (kc&1)*9216 + (w*32 + lq)*36 + lr;
        unsigned a[4][2][4];
        #pragma unroll
        for (int k8 = 0; k8 < 4; ++k8){
            const int kb = k8*8;
            #pragma unroll
            for (int mt = 0; mt < 2; ++mt){
                a[k8][mt][0] = bits(wsA[(mt*16  )*36 + kb    ]);
                a[k8][mt][1] = bits(wsA[(mt*16+8)*36 + kb    ]);
                a[k8][mt][2] = bits(wsA[(mt*16  )*36 + kb + 4]);
                a[k8][mt][3] = bits(wsA[(mt*16+8)*36 + kb + 4]);
            }
        }
        const float* xsB = xcur + lr*72 + lq;
        #pragma unroll
        for (int k8 = 0; k8 < 4; ++k8){
            const int kb = k8*8;
            #pragma unroll
            for (int nt = 0; nt < 8; ++nt){
                unsigned b0 = bits(xsB[ kb   *72 + nt*8]);
                unsigned b1 = bits(xsB[(kb+4)*72 + nt*8]);
                mma8(acc[0][nt], a[k8][0], b0, b1);
                mma8(acc[1][nt], a[k8][1], b0, b1);
            }
        }
        __syncthreads();
    }

    if (ZFUSE){
        if (tid < 64) ZSs[tid] = 1.0f / (zreg + (float)NN);
        __syncthreads();
    }

    // epilogue
    float* Yb = p.Y[y] + (long)b*BCN;
    #pragma unroll
    for (int mt = 0; mt < 2; ++mt){
        #pragma unroll
        for (int half = 0; half < 2; ++half){
            const int r = w*32 + mt*16 + lq + half*8;
            float bi = 0.f;
            if (EPI != EATTN) bi = p.B[y][r];
            const long rowoff = (long)r*NN + n0;
            #pragma unroll
            for (int nt = 0; nt < 8; ++nt){
                const int c = nt*8 + lr*2;
                float x0 = acc[mt][nt][half*2+0] + bi;
                float x1 = acc[mt][nt][half*2+1] + bi;
                float2 o;
                if (EPI == EATTN){
                    const float2 vv = *(const float2*)(p.Vp + (long)b*BCN + rowoff + c);
                    const float2 gg = *(const float2*)(p.Gp + (long)b*BCN + rowoff + c);
                    o.x = (x0 + vv.x) * ZSs[c]   * gg.x;
                    o.y = (x1 + vv.y) * ZSs[c+1] * gg.y;
                } else {
                    o.x = epi_apply(EPI, x0);
                    o.y = epi_apply(EPI, x1);
                }
                *(float2*)(Yb + rowoff + c) = o;
            }
        }
    }
}

// ---------------- kv partial GEMM: P[b][chunk] = k-tile . v-tile^T -----------
__global__ __launch_bounds__(256,2) void kv_kernel(
    const float* __restrict__ K, const float* __restrict__ V, float* __restrict__ P)
{
    extern __shared__ float sm[];
    float* AS = sm;
    float* BS = sm + 2*4608;
    const int tid = threadIdx.x, lane = tid & 31, w = tid >> 5;
    const int lq = lane >> 2, lr = lane & 3;
    const int wm = w & 3, wn = w >> 2;
    const int c0 = (blockIdx.x & 1) * 128;
    const int d0 = (blockIdx.x >> 1) * 128;
    const int chunk = blockIdx.y;
    const int b = blockIdx.z;
    const float* Kb = K + (long)b*BCN;
    const float* Vb = V + (long)b*BCN;
    const long nbase = (long)chunk * 1024;

    {
        const long nb = nbase;
        #pragma unroll
        for (int i = 0; i < 4; ++i){
            int idx = tid + i*256, r = idx >> 3, c4 = idx & 7;
            cpa16(AS + r*36 + c4*4, Kb + (long)(c0+r)*NN + nb + c4*4);
            cpa16(BS + r*36 + c4*4, Vb + (long)(d0+r)*NN + nb + c4*4);
        }
        cpacommit();
    }

    float acc[2][8][4];
    #pragma unroll
    for (int mt = 0; mt < 2; ++mt)
        #pragma unroll
        for (int nt = 0; nt < 8; ++nt)
            #pragma unroll
            for (int i = 0; i < 4; ++i) acc[mt][nt][i] = 0.f;

    #pragma unroll 1
    for (int it = 0; it < 32; ++it){
        cpawait();
        __syncthreads();
        if (it < 31){
            float* as2 = AS + ((it+1)&1)*4608;
            float* bs2 = BS + ((it+1)&1)*4608;
            const long nb = nbase + (long)(it+1)*32;
            #pragma unroll
            for (int i = 0; i < 4; ++i){
                int idx = tid + i*256, r = idx >> 3, c4 = idx & 7;
                cpa16(as2 + r*36 + c4*4, Kb + (long)(c0+r)*NN + nb + c4*4);
                cpa16(bs2 + r*36 + c4*4, Vb + (long)(d0+r)*NN + nb + c4*4);
            }
            cpacommit();
        }
        const float* asA = AS + (it&1)*4608 + (wm*32 + lq)*36 + lr;
        const float* bsB = BS + (it&1)*4608 + (wn*64 + lq)*36 + lr;
        unsigned a[4][2][4];
        #pragma unroll
        for (int k8 = 0; k8 < 4; ++k8){
            const int kb = k8*8;
            #pragma unroll
            for (int mt = 0; mt < 2; ++mt){
                a[k8][mt][0] = bits(asA[(mt*16  )*36 + kb    ]);
                a[k8][mt][1] = bits(asA[(mt*16+8)*36 + kb    ]);
                a[k8][mt][2] = bits(asA[(mt*16  )*36 + kb + 4]);
                a[k8][mt][3] = bits(asA[(mt*16+8)*36 + kb + 4]);
            }
        }
        #pragma unroll
        for (int k8 = 0; k8 < 4; ++k8){
            const int kb = k8*8;
            #pragma unroll
            for (int nt = 0; nt < 8; ++nt){
                unsigned b0 = bits(bsB[nt*8*36 + kb    ]);
                unsigned b1 = bits(bsB[nt*8*36 + kb + 4]);
                mma8(acc[0][nt], a[k8][0], b0, b1);
                mma8(acc[1][nt], a[k8][1], b0, b1);
            }
        }
        __syncthreads();
    }

    float* Pb = P + (long)(b*16 + chunk)*CC*CC;
    #pragma unroll
    for (int mt = 0; mt < 2; ++mt){
        #pragma unroll
        for (int half = 0; half < 2; ++half){
            const int r = c0 + wm*32 + mt*16 + lq + half*8;
            #pragma unroll
            for (int nt = 0; nt < 8; ++nt){
                const int d = d0 + wn*64 + nt*8 + lr*2;
                float2 o;
                o.x = acc[mt][nt][half*2+0];
                o.y = acc[mt][nt][half*2+1];
                *(float2*)(Pb + (long)r*CC + d) = o;
            }
        }
    }
}

// ---------------- kv reduce (+transpose, fold 1/sqrt(C)) ---------------------
__global__ __launch_bounds__(256) void kvred_kernel(
    const float* __restrict__ P, float* __restrict__ kvT)
{
    const int o = blockIdx.x * 256 + threadIdx.x;
    const int b = o >> 16;
    const int c = (o >> 8) & 255;
    const int d = o & 255;
    float s = 0.f;
    #pragma unroll
    for (int ch = 0; ch < 16; ++ch)
        s += P[((long)(b*16 + ch)*256 + c)*256 + d];
    kvT[((long)b*256 + d)*256 + c] = s * (1.0f/16.0f);
}

// ---------------- host side ----------------------------------------------------
static const size_t GEMM_SMEM = (size_t)(2*9216 + 2*2304 + 832) * sizeof(float); // 95488
static const size_t KV_SMEM   = (size_t)(4*4608) * sizeof(float);                // 73728

extern "C" void kernel_launch(void* const* d_in, const int* in_sizes, int n_in,
                              void* d_out, int out_size)
{
    (void)in_sizes; (void)n_in; (void)out_size;
    const float* x   = (const float*)d_in[0];
    const float* Wq1 = (const float*)d_in[1];  const float* bq1 = (const float*)d_in[2];
    const float* Wq2 = (const float*)d_in[3];  const float* bq2 = (const float*)d_in[4];
    const float* Wk1 = (const float*)d_in[5];  const float* bk1 = (const float*)d_in[6];
    const float* Wk2 = (const float*)d_in[7];  const float* bk2 = (const float*)d_in[8];
    const float* Wv  = (const float*)d_in[9];  const float* bv  = (const float*)d_in[10];
    const float* Wg  = (const float*)d_in[11]; const float* bg  = (const float*)d_in[12];
    const float* Wo  = (const float*)d_in[13]; const float* bo  = (const float*)d_in[14];
    float* out = (float*)d_out;

    float *t, *t2, *q, *k, *v, *g, *kvp, *kvT, *ks, *ab;
    cudaGetSymbolAddress((void**)&t,   g_t);
    cudaGetSymbolAddress((void**)&t2,  g_t2);
    cudaGetSymbolAddress((void**)&q,   g_q);
    cudaGetSymbolAddress((void**)&k,   g_k);
    cudaGetSymbolAddress((void**)&v,   g_v);
    cudaGetSymbolAddress((void**)&g,   g_g);
    cudaGetSymbolAddress((void**)&kvp, g_kvp);
    cudaGetSymbolAddress((void**)&kvT, g_kvT);
    cudaGetSymbolAddress((void**)&ks,  g_ks);
    cudaGetSymbolAddress((void**)&ab,  g_ab);

    cudaFuncSetAttribute((const void*)gemm_kernel<1,EGELU,0>,
                         cudaFuncAttributeMaxDynamicSharedMemorySize, (int)GEMM_SMEM);
    cudaFuncSetAttribute((const void*)gemm_kernel<0,ESOFT,0>,
                         cudaFuncAttributeMaxDynamicSharedMemorySize, (int)GEMM_SMEM);
    cudaFuncSetAttribute((const void*)gemm_kernel<0,EATTN,1>,
                         cudaFuncAttributeMaxDynamicSharedMemorySize, (int)GEMM_SMEM);
    cudaFuncSetAttribute((const void*)gemm_kernel<0,EIDENT,0>,
                         cudaFuncAttributeMaxDynamicSharedMemorySize, (int)GEMM_SMEM);
    cudaFuncSetAttribute((const void*)kv_kernel,
                         cudaFuncAttributeMaxDynamicSharedMemorySize, (int)KV_SMEM);

    // 1. norm stats
    stats_kernel<<<BB*CC, 256>>>(x, ab);

    // 2. stage-1 projections (gelu, normalized x): q1->t, k1->t2, v, g
    {
        MP p = {};
        p.W[0]=Wq1; p.B[0]=bq1; p.X[0]=x; p.Y[0]=t;
        p.W[1]=Wk1; p.B[1]=bk1; p.X[1]=x; p.Y[1]=t2;
        p.W[2]=Wv;  p.B[2]=bv;  p.X[2]=x; p.Y[2]=v;
        p.W[3]=Wg;  p.B[3]=bg;  p.X[3]=x; p.Y[3]=g;
        p.AB = ab; p.wBatched = 0;
        dim3 grid(NN/64, 4, BB);
        gemm_kernel<1,EGELU,0><<<grid, 256, GEMM_SMEM>>>(p);
    }

    // 3. stage-2 projections (softplus): q2: t->q, k2: t2->k
    {
        MP p = {};
        p.W[0]=Wq2; p.B[0]=bq2; p.X[0]=t;  p.Y[0]=q;
        p.W[1]=Wk2; p.B[1]=bk2; p.X[1]=t2; p.Y[1]=k;
        p.wBatched = 0;
        dim3 grid(NN/64, 2, BB);
        gemm_kernel<0,ESOFT,0><<<grid, 256, GEMM_SMEM>>>(p);
    }

    // 4. ksum (scaled), kv partials + reduce(+transpose, 1/sqrt(C))
    ksum_kernel<<<BB*CC, 256>>>(k, ks);
    {
        dim3 grid(4, 16, BB);
        kv_kernel<<<grid, 256, KV_SMEM>>>(k, v, kvp);
    }
    kvred_kernel<<<BB*CC, 256>>>(kvp, kvT);

    // 5. attn GEMM with fused z: t = (kvT.q + v) * z * g
    {
        MP p = {};
        p.W[0]=kvT; p.B[0]=nullptr; p.X[0]=q; p.Y[0]=t;
        p.Vp = v; p.Gp = g; p.ksp = ks; p.wBatched = 1;
        dim3 grid(NN/64, 1, BB);
        gemm_kernel<0,EATTN,1><<<grid, 256, GEMM_SMEM>>>(p);
    }

    // 6. final conv1x1: out = Wo.t + bo
    {
        MP p = {};
        p.W[0]=Wo; p.B[0]=bo; p.X[0]=t; p.Y[0]=out;
        p.wBatched = 0;
        dim3 grid(NN/64, 1, BB);
        gemm_kernel<0,EIDENT,0><<<grid, 256, GEMM_SMEM>>>(p);
    }
}